// round 14
// baseline (speedup 1.0000x reference)
#include <cuda_runtime.h>
#include <cuda_bf16.h>
#include <math.h>

// Fixed shapes: N = 12288
#define NPTS   12288
#define NZ     20            // z-slabs (quantile-binned -> ~equal occupancy)
#define TILE   256           // i's per tile (contiguous sorted positions)
#define NTILE  48            // NPTS / TILE
#define CH     16            // chunk-blocks per tile (strided, exact for any R)
#define CHUNK  128           // j's per staged chunk
#define NSTR   8             // fallback stripes per failure
#define FB_BLOCKS 256
#define FINF   (3.0e38f)
#define NEG_BIG (-1.0e30f)
#define FULLMASK 0xFFFFFFFFu

// Device scratch (no allocations). Zero-initialized at load; every run
// restores the zero-invariants it consumes (replay-invariant).
__device__ float4 g_sorted[NPTS];     // z-slab-sorted {x,y,z, bitcast(origIdx)}
__device__ int    g_zbin[NPTS];
__device__ int    g_zhist[NZ];
__device__ int    g_zcur[NZ];
__device__ int    g_zStart[NZ + 1];
__device__ float4 g_cand[CH * NPTS];  // per (chunk-block, i) sorted-desc top-4 of u
__device__ int    g_cnt[NTILE];       // tile merge counters (reset by merger)
__device__ int    g_failCnt;          // reset by bin_kernel each run
__device__ int    g_failList[NPTS];
__device__ float4 g_failD[NPTS];      // {e1,e2,e3,d3} from the scanned range
__device__ float4 g_fbPart[NPTS * NSTR];  // per-stripe triples
__device__ int    g_fbCnt[NPTS];      // per-failure stripe counters (reset by merger)

// Cheap monotone quantile map (logistic approx of gaussian CDF). Must be the
// SAME function at every use site (binning and coverage checks).
__device__ __forceinline__ int binf(float x) {
    float e = exp2f(-2.4554f * x);
    float F = 1.0f / (1.0f + e);
    int c = (int)(F * 20.0f);
    return min(max(c, 0), NZ - 1);
}

// ---- selection networks (validated R2/R3/R10..R13) -----------------------
__device__ __forceinline__ void sort4_full(float u0, float u1, float u2, float u3,
                                           float& s1, float& s2, float& s3, float& s4) {
    float p1 = fmaxf(u0, u1), p2 = fminf(u0, u1);
    float q1 = fmaxf(u2, u3), q2 = fminf(u2, u3);
    s1 = fmaxf(p1, q1);
    float x = fminf(p1, q1);
    float y = fmaxf(p2, q2);
    s2 = fmaxf(x, y);
    s3 = fminf(x, y);
    s4 = fminf(p2, q2);
}

// merge sorted-desc 4-lists, keep top-4
__device__ __forceinline__ void merge4(float& m1, float& m2, float& m3, float& m4,
                                       float s1, float s2, float s3, float s4) {
    float a = fmaxf(m1, s1), b = fminf(m1, s1);
    float c = fmaxf(m2, s2), d = fminf(m2, s2);
    float e = fmaxf(m3, s3);
    float g = fmaxf(m4, s4);
    float t  = fminf(b, c);
    float r2 = fmaxf(b, c);
    float r3 = fmaxf(t, e);
    float l1 = fminf(t, e);
    m1 = a; m2 = r2; m3 = r3;
    m4 = fmaxf(fmaxf(l1, d), g);
}

// ascending insert of d into m1<=m2<=m3
__device__ __forceinline__ void ins3(float d, float& m1, float& m2, float& m3) {
    float t1 = fmaxf(d, m1);  m1 = fminf(d, m1);
    float t2 = fmaxf(t1, m2); m2 = fminf(t1, m2);
    m3 = fminf(t2, m3);
}

// merge two ascending sorted-3 lists, keep 3 smallest
__device__ __forceinline__ void merge3asc(float& m1, float& m2, float& m3,
                                          float s1, float s2, float s3) {
    float a = fminf(m1, s1), b = fmaxf(m1, s1);
    float c = fminf(m2, s2);
    float e = fminf(m3, s3);
    float t = fmaxf(b, c);
    m1 = a; m2 = fminf(b, c); m3 = fminf(t, e);
}

__device__ __forceinline__ void write_cov(float m1a, float m2a, float m3a,
                                          int myi, const float* __restrict__ quat,
                                          float* __restrict__ out) {
    float d1 = sqrtf(m1a), d2s = sqrtf(m2a), d3s = sqrtf(m3a);
    float mean = (d1 + d2s + d3s) * (1.0f / 3.0f);
    float s = 0.001f * fmaxf(mean, 1e-5f);

    float qr = quat[4 * myi + 0];
    float qx = quat[4 * myi + 1];
    float qy = quat[4 * myi + 2];
    float qz = quat[4 * myi + 3];
    float inv = rsqrtf(qr * qr + qx * qx + qy * qy + qz * qz);
    qr *= inv; qx *= inv; qy *= inv; qz *= inv;

    float R00 = 1.0f - 2.0f * (qy * qy + qz * qz);
    float R01 = 2.0f * (qx * qy - qr * qz);
    float R02 = 2.0f * (qx * qz + qr * qy);
    float R10 = 2.0f * (qx * qy + qr * qz);
    float R11 = 1.0f - 2.0f * (qx * qx + qz * qz);
    float R12 = 2.0f * (qy * qz - qr * qx);
    float R20 = 2.0f * (qx * qz - qr * qy);
    float R21 = 2.0f * (qy * qz + qr * qx);
    float R22 = 1.0f - 2.0f * (qx * qx + qy * qy);

    float M00 = s * R00, M01 = s * R01, M02 = s * R02;
    float M10 = s * R10, M11 = s * R11, M12 = s * R12;
    float M20 = s * R20, M21 = s * R21, M22 = s * R22;

    float c00 = M00 * M00 + M01 * M01 + M02 * M02;
    float c01 = M00 * M10 + M01 * M11 + M02 * M12;
    float c02 = M00 * M20 + M01 * M21 + M02 * M22;
    float c11 = M10 * M10 + M11 * M11 + M12 * M12;
    float c12 = M10 * M20 + M11 * M21 + M12 * M22;
    float c22 = M20 * M20 + M21 * M21 + M22 * M22;

    float* o = out + (size_t)myi * 9;
    o[0] = c00; o[1] = c01; o[2] = c02;
    o[3] = c01; o[4] = c11; o[5] = c12;
    o[6] = c02; o[7] = c12; o[8] = c22;
}

// ---- K1: z-bin (also resets fail counter for this run) -------------------
__global__ void bin_kernel(const float* __restrict__ pts) {
    int i = blockIdx.x * blockDim.x + threadIdx.x;
    if (i == 0) g_failCnt = 0;
    if (i >= NPTS) return;
    int zb = binf(pts[3 * i + 2]);
    g_zbin[i] = zb;
    atomicAdd(&g_zhist[zb], 1);
}

// ---- K2: scatter into z-slab-sorted order (prefix computed in-block) -----
__global__ __launch_bounds__(256)
void scatter_kernel(const float* __restrict__ pts) {
    __shared__ int sStart[NZ + 1];
    if (threadIdx.x == 0) {
        int run = 0;
        #pragma unroll
        for (int zpre = 0; zpre < NZ; ++zpre) {
            sStart[zpre] = run;
            run += g_zhist[zpre];
        }
        sStart[NZ] = run;                      // == NPTS
    }
    __syncthreads();

    if (blockIdx.x == 0 && threadIdx.x <= NZ)
        g_zStart[threadIdx.x] = sStart[threadIdx.x];

    int i = blockIdx.x * blockDim.x + threadIdx.x;
    if (i >= NPTS) return;
    int zb = g_zbin[i];
    int pos = sStart[zb] + atomicAdd(&g_zcur[zb], 1);
    g_sorted[pos] = make_float4(pts[3 * i + 0], pts[3 * i + 1], pts[3 * i + 2],
                                __int_as_float(i));
}

// ---- K3: z-slab-pruned brute force + fused merge + coverage check --------
__global__ __launch_bounds__(256)
void chunk_kernel(const float* __restrict__ quat, float* __restrict__ out) {
    __shared__ float4 sh[CHUNK];

    const int tid  = threadIdx.x;
    const int tile = blockIdx.x;
    const int i    = tile * TILE + tid;

    const float4 me = g_sorted[i];
    const float xi = me.x, yi = me.y, zi = me.z;

    const int ztmin = binf(g_sorted[tile * TILE].z);
    const int ztmax = binf(g_sorted[tile * TILE + TILE - 1].z);
    const int zlo = max(ztmin - 1, 0);
    const int zhi = min(ztmax + 1, NZ - 1);
    const int jlo = g_zStart[zlo];
    const int jhi = g_zStart[zhi + 1];
    const int R   = jhi - jlo;

    float m1 = NEG_BIG, m2 = NEG_BIG, m3 = NEG_BIG, m4 = NEG_BIG;

    for (int base = blockIdx.y * CHUNK; base < R; base += CH * CHUNK) {
        const int len = min(CHUNK, R - base);
        __syncthreads();                       // WAR guard vs previous chunk
        if (tid < CHUNK) {
            if (tid < len) {
                float4 q = g_sorted[jlo + base + tid];
                q.w = 0.5f * (q.x * q.x + q.y * q.y + q.z * q.z);
                sh[tid] = q;
            } else {
                sh[tid] = make_float4(0.0f, 0.0f, 0.0f, FINF);   // u = -huge
            }
        }
        __syncthreads();
        #pragma unroll 2
        for (int t = 0; t < CHUNK; t += 4) {
            float4 p0 = sh[t], p1 = sh[t + 1], p2 = sh[t + 2], p3 = sh[t + 3];
            float u0 = fmaf(zi, p0.z, fmaf(yi, p0.y, fmaf(xi, p0.x, -p0.w)));
            float u1 = fmaf(zi, p1.z, fmaf(yi, p1.y, fmaf(xi, p1.x, -p1.w)));
            float u2 = fmaf(zi, p2.z, fmaf(yi, p2.y, fmaf(xi, p2.x, -p2.w)));
            float u3 = fmaf(zi, p3.z, fmaf(yi, p3.y, fmaf(xi, p3.x, -p3.w)));
            float s1, s2, s3, s4;
            sort4_full(u0, u1, u2, u3, s1, s2, s3, s4);
            merge4(m1, m2, m3, m4, s1, s2, s3, s4);
        }
    }

    g_cand[blockIdx.y * NPTS + i] = make_float4(m1, m2, m3, m4);

    // ---- fused merge: last-arriving block of this tile ----
    __threadfence();
    __shared__ int sLast;
    if (tid == 0)
        sLast = (atomicAdd(&g_cnt[tile], 1) == CH - 1) ? 1 : 0;
    __syncthreads();
    if (!sLast) return;
    __threadfence();

    float4 c0 = g_cand[0 * NPTS + i];
    float w1 = c0.x, w2 = c0.y, w3 = c0.z, w4 = c0.w;
    #pragma unroll
    for (int s = 1; s < CH; ++s) {
        float4 cc = g_cand[s * NPTS + i];
        merge4(w1, w2, w3, w4, cc.x, cc.y, cc.z, cc.w);
    }
    // w1 == u_self (strict global max within range); NNs are w2..w4.
    const float sqi = xi * xi + yi * yi + zi * zi;
    float e1 = fmaxf(fmaf(-2.0f, w2, sqi), 0.0f);   // d^2 ascending
    float e2 = fmaxf(fmaf(-2.0f, w3, sqi), 0.0f);
    float e3 = fmaxf(fmaf(-2.0f, w4, sqi), 0.0f);
    float d3 = sqrtf(e3);

    // exactness: ball of radius d3 must lie within scanned z-slabs
    if (binf(zi - d3) >= zlo && binf(zi + d3) <= zhi) {
        write_cov(e1, e2, e3, __float_as_int(me.w), quat, out);
    } else {
        int pos = atomicAdd(&g_failCnt, 1);
        g_failList[pos] = i;                   // striped delta-scan finishes it
        g_failD[pos]    = make_float4(e1, e2, e3, d3);
    }

    if (tid == 0) g_cnt[tile] = 0;             // reset for next graph replay
}

// ---- K4: striped delta fallback ------------------------------------------
// Delta region (slabs [binf(z-d3), zlo) and (zhi, binf(z+d3)]) is disjoint
// from the chunk-scanned region. Work item = (failure, stripe s of 8): each
// warp scans 1/8 of the flattened delta range; the 8th-arriving warp merges
// the 8 stripe triples + the stored covered-region triple once -> exact
// top-3 of the union. Caps worst-warp work for tail points whose delta
// spans thousands of points.
__global__ __launch_bounds__(256)
void fallback_kernel(const float* __restrict__ quat, float* __restrict__ out) {
    const int gw     = (blockIdx.x * 256 + threadIdx.x) >> 5;
    const int lane   = threadIdx.x & 31;
    const int nWarps = FB_BLOCKS * 8;
    const int nItems = g_failCnt * NSTR;

    for (int item = gw; item < nItems; item += nWarps) {
        const int f = item >> 3;               // failure index
        const int s = item & (NSTR - 1);       // stripe index
        const int p     = g_failList[f];
        const float4 ed = g_failD[f];          // {e1,e2,e3,d3}
        const float4 me = g_sorted[p];

        // recompute the tile's scanned slab range (deterministic)
        const int tile  = p / TILE;
        const int ztmin = binf(g_sorted[tile * TILE].z);
        const int ztmax = binf(g_sorted[tile * TILE + TILE - 1].z);
        const int zlo   = max(ztmin - 1, 0);
        const int zhi   = min(ztmax + 1, NZ - 1);
        const int zl    = binf(me.z - ed.w);
        const int zh    = binf(me.z + ed.w);

        // two disjoint uncovered ranges (either may be empty), flattened
        const int aLo = g_zStart[zl],               aHi = g_zStart[max(zl, zlo)];
        const int bLo = g_zStart[min(zh, zhi) + 1], bHi = g_zStart[zh + 1];
        const int lenA = aHi - aLo;
        const int L    = lenA + (bHi - bLo);

        const int f0 = (s * L) >> 3;           // this stripe: [f0, f1)
        const int f1 = ((s + 1) * L) >> 3;

        float m1 = FINF, m2 = FINF, m3 = FINF;
        for (int idx = f0 + lane; idx < f1; idx += 32) {
            int t = (idx < lenA) ? (aLo + idx) : (bLo + (idx - lenA));
            float4 q = g_sorted[t];
            float dx = me.x - q.x, dy = me.y - q.y, dz = me.z - q.z;
            ins3(fmaf(dz, dz, fmaf(dy, dy, dx * dx)), m1, m2, m3);
        }
        #pragma unroll
        for (int off = 16; off >= 1; off >>= 1) {
            float s1 = __shfl_xor_sync(FULLMASK, m1, off);
            float s2 = __shfl_xor_sync(FULLMASK, m2, off);
            float s3 = __shfl_xor_sync(FULLMASK, m3, off);
            merge3asc(m1, m2, m3, s1, s2, s3);
        }

        if (lane == 0) {
            g_fbPart[f * NSTR + s] = make_float4(m1, m2, m3, 0.0f);
            __threadfence();                   // release stripe triple
            int cnt = atomicAdd(&g_fbCnt[f], 1);
            if (cnt == NSTR - 1) {             // last stripe: merge + write
                __threadfence();               // acquire other stripes
                float r1 = ed.x, r2 = ed.y, r3 = ed.z;
                #pragma unroll
                for (int k = 0; k < NSTR; ++k) {
                    float4 c = g_fbPart[f * NSTR + k];
                    merge3asc(r1, r2, r3, c.x, c.y, c.z);
                }
                g_fbCnt[f] = 0;                // reset for next replay
                write_cov(r1, r2, r3, __float_as_int(me.w), quat, out);
            }
        }
    }

    // restore zero-invariants for the next graph replay
    if (blockIdx.x == 0 && threadIdx.x < NZ) {
        g_zhist[threadIdx.x] = 0;
        g_zcur[threadIdx.x]  = 0;
    }
}

extern "C" void kernel_launch(void* const* d_in, const int* in_sizes, int n_in,
                              void* d_out, int out_size) {
    const float* pts  = (const float*)d_in[0];   // (N, 3) float32
    const float* quat = (const float*)d_in[1];   // (N, 4) float32
    float* out = (float*)d_out;                  // (N, 3, 3) float32

    bin_kernel     <<<(NPTS + 255) / 256, 256>>>(pts);
    scatter_kernel <<<(NPTS + 255) / 256, 256>>>(pts);
    dim3 grid(NTILE, CH);
    chunk_kernel   <<<grid, 256>>>(quat, out);
    fallback_kernel<<<FB_BLOCKS, 256>>>(quat, out);
}

// round 15
// speedup vs baseline: 1.0393x; 1.0393x over previous
#include <cuda_runtime.h>
#include <cuda_bf16.h>
#include <math.h>

// Fixed shapes: N = 12288
#define NPTS   12288
#define NZ     128           // fine z-slabs (quantile-binned, ~96 pts each)
#define MARG   8             // chunk margin in fine slabs (~0.16 z at core)
#define TILE   256           // i's per tile (contiguous sorted positions)
#define NTILE  48            // NPTS / TILE
#define CH     20            // chunk-blocks per tile (strided, exact for any R)
#define CHUNK  128           // j's per staged chunk
#define TPB    128           // chunk block size (2 points per thread)
#define FB_BLOCKS 192
#define FINF   (3.0e38f)
#define NEG_BIG (-1.0e30f)
#define FULLMASK 0xFFFFFFFFu

// Device scratch (no allocations). Zero at load; every run restores the
// zero-invariants it consumes (replay-invariant).
__device__ float4 g_sorted[NPTS];     // z-slab-sorted {x,y,z, bitcast(origIdx)}
__device__ int    g_zbin[NPTS];
__device__ int    g_zhist[NZ];
__device__ int    g_zcur[NZ];
__device__ int    g_zStart[NZ + 1];
__device__ float4 g_cand[CH * NPTS];  // per (chunk-block, i) sorted-desc top-4 of u
__device__ int    g_cnt[NTILE];       // tile merge counters (reset by merger)
__device__ int    g_failCnt;          // reset by bin_kernel each run
__device__ int    g_failList[NPTS];
__device__ float4 g_failD[NPTS];      // {e1,e2,e3,d3} from the scanned range

// Cheap monotone quantile map (logistic approx of gaussian CDF). Must be the
// SAME function at every use site (binning and coverage checks).
__device__ __forceinline__ int binf(float x) {
    float e = exp2f(-2.4554f * x);
    float F = 1.0f / (1.0f + e);
    int c = (int)(F * (float)NZ);
    return min(max(c, 0), NZ - 1);
}

// ---- selection networks (validated R2/R3/R10..R14) -----------------------
__device__ __forceinline__ void sort4_full(float u0, float u1, float u2, float u3,
                                           float& s1, float& s2, float& s3, float& s4) {
    float p1 = fmaxf(u0, u1), p2 = fminf(u0, u1);
    float q1 = fmaxf(u2, u3), q2 = fminf(u2, u3);
    s1 = fmaxf(p1, q1);
    float x = fminf(p1, q1);
    float y = fmaxf(p2, q2);
    s2 = fmaxf(x, y);
    s3 = fminf(x, y);
    s4 = fminf(p2, q2);
}

// merge sorted-desc 4-lists, keep top-4
__device__ __forceinline__ void merge4(float& m1, float& m2, float& m3, float& m4,
                                       float s1, float s2, float s3, float s4) {
    float a = fmaxf(m1, s1), b = fminf(m1, s1);
    float c = fmaxf(m2, s2), d = fminf(m2, s2);
    float e = fmaxf(m3, s3);
    float g = fmaxf(m4, s4);
    float t  = fminf(b, c);
    float r2 = fmaxf(b, c);
    float r3 = fmaxf(t, e);
    float l1 = fminf(t, e);
    m1 = a; m2 = r2; m3 = r3;
    m4 = fmaxf(fmaxf(l1, d), g);
}

// ascending insert of d into m1<=m2<=m3
__device__ __forceinline__ void ins3(float d, float& m1, float& m2, float& m3) {
    float t1 = fmaxf(d, m1);  m1 = fminf(d, m1);
    float t2 = fmaxf(t1, m2); m2 = fminf(t1, m2);
    m3 = fminf(t2, m3);
}

// merge two ascending sorted-3 lists, keep 3 smallest
__device__ __forceinline__ void merge3asc(float& m1, float& m2, float& m3,
                                          float s1, float s2, float s3) {
    float a = fminf(m1, s1), b = fmaxf(m1, s1);
    float c = fminf(m2, s2);
    float e = fminf(m3, s3);
    float t = fmaxf(b, c);
    m1 = a; m2 = fminf(b, c); m3 = fminf(t, e);
}

__device__ __forceinline__ void write_cov(float m1a, float m2a, float m3a,
                                          int myi, const float* __restrict__ quat,
                                          float* __restrict__ out) {
    float d1 = sqrtf(m1a), d2s = sqrtf(m2a), d3s = sqrtf(m3a);
    float mean = (d1 + d2s + d3s) * (1.0f / 3.0f);
    float s = 0.001f * fmaxf(mean, 1e-5f);

    float qr = quat[4 * myi + 0];
    float qx = quat[4 * myi + 1];
    float qy = quat[4 * myi + 2];
    float qz = quat[4 * myi + 3];
    float inv = rsqrtf(qr * qr + qx * qx + qy * qy + qz * qz);
    qr *= inv; qx *= inv; qy *= inv; qz *= inv;

    float R00 = 1.0f - 2.0f * (qy * qy + qz * qz);
    float R01 = 2.0f * (qx * qy - qr * qz);
    float R02 = 2.0f * (qx * qz + qr * qy);
    float R10 = 2.0f * (qx * qy + qr * qz);
    float R11 = 1.0f - 2.0f * (qx * qx + qz * qz);
    float R12 = 2.0f * (qy * qz - qr * qx);
    float R20 = 2.0f * (qx * qz - qr * qy);
    float R21 = 2.0f * (qy * qz + qr * qx);
    float R22 = 1.0f - 2.0f * (qx * qx + qy * qy);

    float M00 = s * R00, M01 = s * R01, M02 = s * R02;
    float M10 = s * R10, M11 = s * R11, M12 = s * R12;
    float M20 = s * R20, M21 = s * R21, M22 = s * R22;

    float c00 = M00 * M00 + M01 * M01 + M02 * M02;
    float c01 = M00 * M10 + M01 * M11 + M02 * M12;
    float c02 = M00 * M20 + M01 * M21 + M02 * M22;
    float c11 = M10 * M10 + M11 * M11 + M12 * M12;
    float c12 = M10 * M20 + M11 * M21 + M12 * M22;
    float c22 = M20 * M20 + M21 * M21 + M22 * M22;

    float* o = out + (size_t)myi * 9;
    o[0] = c00; o[1] = c01; o[2] = c02;
    o[3] = c01; o[4] = c11; o[5] = c12;
    o[6] = c02; o[7] = c12; o[8] = c22;
}

// ---- K1: z-bin (also resets fail counter for this run) -------------------
__global__ void bin_kernel(const float* __restrict__ pts) {
    int i = blockIdx.x * blockDim.x + threadIdx.x;
    if (i == 0) g_failCnt = 0;
    if (i >= NPTS) return;
    int zb = binf(pts[3 * i + 2]);
    g_zbin[i] = zb;
    atomicAdd(&g_zhist[zb], 1);
}

// ---- K2: scatter into z-slab-sorted order (prefix computed in-block) -----
__global__ __launch_bounds__(256)
void scatter_kernel(const float* __restrict__ pts) {
    __shared__ int sStart[NZ + 1];
    if (threadIdx.x == 0) {
        int run = 0;
        for (int zpre = 0; zpre < NZ; ++zpre) {
            sStart[zpre] = run;
            run += g_zhist[zpre];
        }
        sStart[NZ] = run;                      // == NPTS
    }
    __syncthreads();

    if (blockIdx.x == 0 && threadIdx.x <= NZ)
        g_zStart[threadIdx.x] = sStart[threadIdx.x];

    int i = blockIdx.x * blockDim.x + threadIdx.x;
    if (i >= NPTS) return;
    int zb = g_zbin[i];
    int pos = sStart[zb] + atomicAdd(&g_zcur[zb], 1);
    g_sorted[pos] = make_float4(pts[3 * i + 0], pts[3 * i + 1], pts[3 * i + 2],
                                __int_as_float(i));
}

// ---- K3: z-window-pruned brute force, 2 points/thread --------------------
// grid (NTILE, CH), 128 threads. Tile j-range = fine slabs
// [ztmin-MARG, ztmax+MARG]; strided CHUNK windows staged to smem; top-4 of
// u = p.q - 0.5|q|^2 per point (self = strict max, dropped at merge).
__global__ __launch_bounds__(TPB)
void chunk_kernel(const float* __restrict__ quat, float* __restrict__ out) {
    __shared__ float4 sh[CHUNK];

    const int tid  = threadIdx.x;
    const int tile = blockIdx.x;
    const int i0   = tile * TILE + tid;
    const int i1   = i0 + TPB;

    const float4 meA = g_sorted[i0];
    const float4 meB = g_sorted[i1];
    const float xa = meA.x, ya = meA.y, za = meA.z;
    const float xb = meB.x, yb = meB.y, zb = meB.z;

    const int ztmin = binf(g_sorted[tile * TILE].z);
    const int ztmax = binf(g_sorted[tile * TILE + TILE - 1].z);
    const int zlo = max(ztmin - MARG, 0);
    const int zhi = min(ztmax + MARG, NZ - 1);
    const int jlo = g_zStart[zlo];
    const int jhi = g_zStart[zhi + 1];
    const int R   = jhi - jlo;

    float a1 = NEG_BIG, a2 = NEG_BIG, a3 = NEG_BIG, a4 = NEG_BIG;
    float b1 = NEG_BIG, b2 = NEG_BIG, b3 = NEG_BIG, b4 = NEG_BIG;

    for (int base = blockIdx.y * CHUNK; base < R; base += CH * CHUNK) {
        const int len = min(CHUNK, R - base);
        __syncthreads();                       // WAR guard vs previous chunk
        if (tid < len) {
            float4 q = g_sorted[jlo + base + tid];
            q.w = 0.5f * (q.x * q.x + q.y * q.y + q.z * q.z);
            sh[tid] = q;
        } else {
            sh[tid] = make_float4(0.0f, 0.0f, 0.0f, FINF);   // u = -huge
        }
        __syncthreads();
        #pragma unroll 2
        for (int t = 0; t < CHUNK; t += 4) {
            float4 p0 = sh[t], p1 = sh[t + 1], p2 = sh[t + 2], p3 = sh[t + 3];
            {
                float u0 = fmaf(za, p0.z, fmaf(ya, p0.y, fmaf(xa, p0.x, -p0.w)));
                float u1 = fmaf(za, p1.z, fmaf(ya, p1.y, fmaf(xa, p1.x, -p1.w)));
                float u2 = fmaf(za, p2.z, fmaf(ya, p2.y, fmaf(xa, p2.x, -p2.w)));
                float u3 = fmaf(za, p3.z, fmaf(ya, p3.y, fmaf(xa, p3.x, -p3.w)));
                float s1, s2, s3, s4;
                sort4_full(u0, u1, u2, u3, s1, s2, s3, s4);
                merge4(a1, a2, a3, a4, s1, s2, s3, s4);
            }
            {
                float u0 = fmaf(zb, p0.z, fmaf(yb, p0.y, fmaf(xb, p0.x, -p0.w)));
                float u1 = fmaf(zb, p1.z, fmaf(yb, p1.y, fmaf(xb, p1.x, -p1.w)));
                float u2 = fmaf(zb, p2.z, fmaf(yb, p2.y, fmaf(xb, p2.x, -p2.w)));
                float u3 = fmaf(zb, p3.z, fmaf(yb, p3.y, fmaf(xb, p3.x, -p3.w)));
                float s1, s2, s3, s4;
                sort4_full(u0, u1, u2, u3, s1, s2, s3, s4);
                merge4(b1, b2, b3, b4, s1, s2, s3, s4);
            }
        }
    }

    g_cand[blockIdx.y * NPTS + i0] = make_float4(a1, a2, a3, a4);
    g_cand[blockIdx.y * NPTS + i1] = make_float4(b1, b2, b3, b4);

    // ---- fused merge: last-arriving block of this tile ----
    __threadfence();
    __shared__ int sLast;
    if (tid == 0)
        sLast = (atomicAdd(&g_cnt[tile], 1) == CH - 1) ? 1 : 0;
    __syncthreads();
    if (!sLast) return;
    __threadfence();

    #pragma unroll
    for (int k = 0; k < 2; ++k) {
        const int i = tile * TILE + tid + k * TPB;
        const float4 me = (k == 0) ? meA : meB;

        float4 c0 = g_cand[0 * NPTS + i];
        float w1 = c0.x, w2 = c0.y, w3 = c0.z, w4 = c0.w;
        #pragma unroll
        for (int s = 1; s < CH; ++s) {
            float4 cc = g_cand[s * NPTS + i];
            merge4(w1, w2, w3, w4, cc.x, cc.y, cc.z, cc.w);
        }
        // w1 == u_self (strict global max within range); NNs are w2..w4.
        const float sqi = me.x * me.x + me.y * me.y + me.z * me.z;
        float e1 = fmaxf(fmaf(-2.0f, w2, sqi), 0.0f);   // d^2 ascending
        float e2 = fmaxf(fmaf(-2.0f, w3, sqi), 0.0f);
        float e3 = fmaxf(fmaf(-2.0f, w4, sqi), 0.0f);
        float d3 = sqrtf(e3);

        // exactness: ball of radius d3 must lie within scanned slabs
        if (binf(me.z - d3) >= zlo && binf(me.z + d3) <= zhi) {
            write_cov(e1, e2, e3, __float_as_int(me.w), quat, out);
        } else {
            int pos = atomicAdd(&g_failCnt, 1);
            g_failList[pos] = i;                   // delta-scan finishes it
            g_failD[pos]    = make_float4(e1, e2, e3, d3);
        }
    }

    if (tid == 0) g_cnt[tile] = 0;             // reset for next graph replay
}

// ---- K4: delta fallback — warp-per-failure over uncovered slabs ----------
// Delta slabs [binf(z-d3), zlo) and (zhi, binf(z+d3)] are disjoint from the
// chunk-scanned region; with fine bins these are small (excess beyond the
// MARG margin). Fresh warp triple merged ONCE (lane 0) with stored triple.
__global__ __launch_bounds__(256)
void fallback_kernel(const float* __restrict__ quat, float* __restrict__ out) {
    const int gw   = (blockIdx.x * 256 + threadIdx.x) >> 5;
    const int lane = threadIdx.x & 31;
    const int nf   = g_failCnt;

    for (int f = gw; f < nf; f += (FB_BLOCKS * 8)) {
        const int p     = g_failList[f];
        const float4 ed = g_failD[f];          // {e1,e2,e3,d3}
        const float4 me = g_sorted[p];

        // recompute the tile's scanned slab range (deterministic)
        const int tile  = p / TILE;
        const int ztmin = binf(g_sorted[tile * TILE].z);
        const int ztmax = binf(g_sorted[tile * TILE + TILE - 1].z);
        const int zlo   = max(ztmin - MARG, 0);
        const int zhi   = min(ztmax + MARG, NZ - 1);
        const int zl    = binf(me.z - ed.w);
        const int zh    = binf(me.z + ed.w);

        // two disjoint uncovered ranges (either may be empty)
        const int aLo = g_zStart[zl],               aHi = g_zStart[max(zl, zlo)];
        const int bLo = g_zStart[min(zh, zhi) + 1], bHi = g_zStart[zh + 1];

        float m1 = FINF, m2 = FINF, m3 = FINF;
        #pragma unroll 4
        for (int t = aLo + lane; t < aHi; t += 32) {
            float4 q = g_sorted[t];
            float dx = me.x - q.x, dy = me.y - q.y, dz = me.z - q.z;
            ins3(fmaf(dz, dz, fmaf(dy, dy, dx * dx)), m1, m2, m3);
        }
        #pragma unroll 4
        for (int t = bLo + lane; t < bHi; t += 32) {
            float4 q = g_sorted[t];
            float dx = me.x - q.x, dy = me.y - q.y, dz = me.z - q.z;
            ins3(fmaf(dz, dz, fmaf(dy, dy, dx * dx)), m1, m2, m3);
        }
        #pragma unroll
        for (int off = 16; off >= 1; off >>= 1) {
            float s1 = __shfl_xor_sync(FULLMASK, m1, off);
            float s2 = __shfl_xor_sync(FULLMASK, m2, off);
            float s3 = __shfl_xor_sync(FULLMASK, m3, off);
            merge3asc(m1, m2, m3, s1, s2, s3);
        }
        if (lane == 0) {
            merge3asc(m1, m2, m3, ed.x, ed.y, ed.z);   // union with scanned triple
            write_cov(m1, m2, m3, __float_as_int(me.w), quat, out);
        }
    }

    // restore zero-invariants for the next graph replay
    if (blockIdx.x == 0 && threadIdx.x < NZ) {
        g_zhist[threadIdx.x] = 0;
        g_zcur[threadIdx.x]  = 0;
    }
}

extern "C" void kernel_launch(void* const* d_in, const int* in_sizes, int n_in,
                              void* d_out, int out_size) {
    const float* pts  = (const float*)d_in[0];   // (N, 3) float32
    const float* quat = (const float*)d_in[1];   // (N, 4) float32
    float* out = (float*)d_out;                  // (N, 3, 3) float32

    bin_kernel     <<<(NPTS + 255) / 256, 256>>>(pts);
    scatter_kernel <<<(NPTS + 255) / 256, 256>>>(pts);
    dim3 grid(NTILE, CH);
    chunk_kernel   <<<grid, TPB>>>(quat, out);
    fallback_kernel<<<FB_BLOCKS, 256>>>(quat, out);
}

// round 16
// speedup vs baseline: 1.3317x; 1.2814x over previous
#include <cuda_runtime.h>
#include <cuda_bf16.h>
#include <math.h>

// Fixed shapes: N = 12288
#define NPTS   12288
#define NZ     128           // fine RADIAL shells (quantile-binned, ~96 pts each)
#define MARG   14            // chunk margin in shells (~1350 pts per side)
#define TILE   256           // i's per tile (contiguous sorted positions)
#define NTILE  48            // NPTS / TILE
#define CH     24            // chunk-blocks per tile (strided, exact for any R)
#define CHUNK  128           // j's per staged chunk
#define TPB    128           // chunk block size (2 points per thread)
#define FB_BLOCKS 192
#define FINF   (3.0e38f)
#define NEG_BIG (-1.0e30f)
#define FULLMASK 0xFFFFFFFFu

// Device scratch (no allocations). Zero at load; every run restores the
// zero-invariants it consumes (replay-invariant).
__device__ float4 g_sorted[NPTS];     // shell-sorted {x,y,z, bitcast(origIdx)}
__device__ int    g_bin[NPTS];        // per-ORIGINAL-index shell bin
__device__ int    g_sbin[NPTS];       // per-SORTED-position shell bin
__device__ int    g_zhist[NZ];
__device__ int    g_zcur[NZ];
__device__ int    g_zStart[NZ + 1];
__device__ float4 g_cand[CH * NPTS];  // per (chunk-block, i) sorted-desc top-4 of u
__device__ int    g_cnt[NTILE];       // tile merge counters (reset by merger)
__device__ int    g_failCnt;          // reset by bin_kernel each run
__device__ int    g_failList[NPTS];
__device__ float4 g_failD[NPTS];      // {e1,e2,e3,d3} from the scanned range

// Monotone radial quantile map: chi-3 CDF approx
//   F(r) = 2*sigmoid(1.702 r) - 1 - sqrt(2/pi) * r * exp(-r^2/2)
// Monotone (F' > 0 checked analytically); rough equal-occupancy is all we need.
// Negative inputs clamp to bin 0. Same function at every use site.
__device__ __forceinline__ int binf(float r) {
    float sig = 1.0f / (1.0f + exp2f(-2.4554f * r));          // sigmoid(1.702 r)
    float gs  = exp2f(-0.72134752f * r * r);                  // exp(-r^2/2)
    float F   = fmaf(2.0f, sig, -1.0f) - 0.79788456f * r * gs;
    int c = (int)(F * (float)NZ);
    return min(max(c, 0), NZ - 1);
}

// ---- selection networks (validated R2/R3/R10..R15) -----------------------
__device__ __forceinline__ void sort4_full(float u0, float u1, float u2, float u3,
                                           float& s1, float& s2, float& s3, float& s4) {
    float p1 = fmaxf(u0, u1), p2 = fminf(u0, u1);
    float q1 = fmaxf(u2, u3), q2 = fminf(u2, u3);
    s1 = fmaxf(p1, q1);
    float x = fminf(p1, q1);
    float y = fmaxf(p2, q2);
    s2 = fmaxf(x, y);
    s3 = fminf(x, y);
    s4 = fminf(p2, q2);
}

// merge sorted-desc 4-lists, keep top-4
__device__ __forceinline__ void merge4(float& m1, float& m2, float& m3, float& m4,
                                       float s1, float s2, float s3, float s4) {
    float a = fmaxf(m1, s1), b = fminf(m1, s1);
    float c = fmaxf(m2, s2), d = fminf(m2, s2);
    float e = fmaxf(m3, s3);
    float g = fmaxf(m4, s4);
    float t  = fminf(b, c);
    float r2 = fmaxf(b, c);
    float r3 = fmaxf(t, e);
    float l1 = fminf(t, e);
    m1 = a; m2 = r2; m3 = r3;
    m4 = fmaxf(fmaxf(l1, d), g);
}

// ascending insert of d into m1<=m2<=m3
__device__ __forceinline__ void ins3(float d, float& m1, float& m2, float& m3) {
    float t1 = fmaxf(d, m1);  m1 = fminf(d, m1);
    float t2 = fmaxf(t1, m2); m2 = fminf(t1, m2);
    m3 = fminf(t2, m3);
}

// merge two ascending sorted-3 lists, keep 3 smallest
__device__ __forceinline__ void merge3asc(float& m1, float& m2, float& m3,
                                          float s1, float s2, float s3) {
    float a = fminf(m1, s1), b = fmaxf(m1, s1);
    float c = fminf(m2, s2);
    float e = fminf(m3, s3);
    float t = fmaxf(b, c);
    m1 = a; m2 = fminf(b, c); m3 = fminf(t, e);
}

__device__ __forceinline__ void write_cov(float m1a, float m2a, float m3a,
                                          int myi, const float* __restrict__ quat,
                                          float* __restrict__ out) {
    float d1 = sqrtf(m1a), d2s = sqrtf(m2a), d3s = sqrtf(m3a);
    float mean = (d1 + d2s + d3s) * (1.0f / 3.0f);
    float s = 0.001f * fmaxf(mean, 1e-5f);

    float qr = quat[4 * myi + 0];
    float qx = quat[4 * myi + 1];
    float qy = quat[4 * myi + 2];
    float qz = quat[4 * myi + 3];
    float inv = rsqrtf(qr * qr + qx * qx + qy * qy + qz * qz);
    qr *= inv; qx *= inv; qy *= inv; qz *= inv;

    float R00 = 1.0f - 2.0f * (qy * qy + qz * qz);
    float R01 = 2.0f * (qx * qy - qr * qz);
    float R02 = 2.0f * (qx * qz + qr * qy);
    float R10 = 2.0f * (qx * qy + qr * qz);
    float R11 = 1.0f - 2.0f * (qx * qx + qz * qz);
    float R12 = 2.0f * (qy * qz - qr * qx);
    float R20 = 2.0f * (qx * qz - qr * qy);
    float R21 = 2.0f * (qy * qz + qr * qx);
    float R22 = 1.0f - 2.0f * (qx * qx + qy * qy);

    float M00 = s * R00, M01 = s * R01, M02 = s * R02;
    float M10 = s * R10, M11 = s * R11, M12 = s * R12;
    float M20 = s * R20, M21 = s * R21, M22 = s * R22;

    float c00 = M00 * M00 + M01 * M01 + M02 * M02;
    float c01 = M00 * M10 + M01 * M11 + M02 * M12;
    float c02 = M00 * M20 + M01 * M21 + M02 * M22;
    float c11 = M10 * M10 + M11 * M11 + M12 * M12;
    float c12 = M10 * M20 + M11 * M21 + M12 * M22;
    float c22 = M20 * M20 + M21 * M21 + M22 * M22;

    float* o = out + (size_t)myi * 9;
    o[0] = c00; o[1] = c01; o[2] = c02;
    o[3] = c01; o[4] = c11; o[5] = c12;
    o[6] = c02; o[7] = c12; o[8] = c22;
}

// ---- K1: radial-shell bin (also resets fail counter) ---------------------
__global__ void bin_kernel(const float* __restrict__ pts) {
    int i = blockIdx.x * blockDim.x + threadIdx.x;
    if (i == 0) g_failCnt = 0;
    if (i >= NPTS) return;
    float x = pts[3 * i + 0], y = pts[3 * i + 1], z = pts[3 * i + 2];
    float r = sqrtf(x * x + y * y + z * z);
    int zb = binf(r);
    g_bin[i] = zb;
    atomicAdd(&g_zhist[zb], 1);
}

// ---- K2: scatter into shell-sorted order (prefix computed in-block) ------
__global__ __launch_bounds__(256)
void scatter_kernel(const float* __restrict__ pts) {
    __shared__ int sStart[NZ + 1];
    if (threadIdx.x == 0) {
        int run = 0;
        for (int zpre = 0; zpre < NZ; ++zpre) {
            sStart[zpre] = run;
            run += g_zhist[zpre];
        }
        sStart[NZ] = run;                      // == NPTS
    }
    __syncthreads();

    if (blockIdx.x == 0 && threadIdx.x <= NZ)
        g_zStart[threadIdx.x] = sStart[threadIdx.x];

    int i = blockIdx.x * blockDim.x + threadIdx.x;
    if (i >= NPTS) return;
    int zb = g_bin[i];
    int pos = sStart[zb] + atomicAdd(&g_zcur[zb], 1);
    g_sorted[pos] = make_float4(pts[3 * i + 0], pts[3 * i + 1], pts[3 * i + 2],
                                __int_as_float(i));
    g_sbin[pos] = zb;
}

// ---- K3: shell-window-pruned brute force, 2 points/thread ----------------
// grid (NTILE, CH), 128 threads. Tile j-range = shells [smin-MARG, smax+MARG]
// (exact ints from g_sbin endpoints); strided CHUNK windows staged to smem;
// top-4 of u = p.q - 0.5|q|^2 per point (self = strict max, dropped at merge).
// Exactness: |r_q - r_p| <= d(q,p), so all true NNs lie within +-d3 in radius.
__global__ __launch_bounds__(TPB)
void chunk_kernel(const float* __restrict__ quat, float* __restrict__ out) {
    __shared__ float4 sh[CHUNK];

    const int tid  = threadIdx.x;
    const int tile = blockIdx.x;
    const int i0   = tile * TILE + tid;
    const int i1   = i0 + TPB;

    const float4 meA = g_sorted[i0];
    const float4 meB = g_sorted[i1];
    const float xa = meA.x, ya = meA.y, za = meA.z;
    const float xb = meB.x, yb = meB.y, zb = meB.z;

    const int smin = g_sbin[tile * TILE];
    const int smax = g_sbin[tile * TILE + TILE - 1];
    const int zlo = max(smin - MARG, 0);
    const int zhi = min(smax + MARG, NZ - 1);
    const int jlo = g_zStart[zlo];
    const int jhi = g_zStart[zhi + 1];
    const int R   = jhi - jlo;

    float a1 = NEG_BIG, a2 = NEG_BIG, a3 = NEG_BIG, a4 = NEG_BIG;
    float b1 = NEG_BIG, b2 = NEG_BIG, b3 = NEG_BIG, b4 = NEG_BIG;

    for (int base = blockIdx.y * CHUNK; base < R; base += CH * CHUNK) {
        const int len = min(CHUNK, R - base);
        __syncthreads();                       // WAR guard vs previous chunk
        if (tid < len) {
            float4 q = g_sorted[jlo + base + tid];
            q.w = 0.5f * (q.x * q.x + q.y * q.y + q.z * q.z);
            sh[tid] = q;
        } else {
            sh[tid] = make_float4(0.0f, 0.0f, 0.0f, FINF);   // u = -huge
        }
        __syncthreads();
        #pragma unroll 2
        for (int t = 0; t < CHUNK; t += 4) {
            float4 p0 = sh[t], p1 = sh[t + 1], p2 = sh[t + 2], p3 = sh[t + 3];
            {
                float u0 = fmaf(za, p0.z, fmaf(ya, p0.y, fmaf(xa, p0.x, -p0.w)));
                float u1 = fmaf(za, p1.z, fmaf(ya, p1.y, fmaf(xa, p1.x, -p1.w)));
                float u2 = fmaf(za, p2.z, fmaf(ya, p2.y, fmaf(xa, p2.x, -p2.w)));
                float u3 = fmaf(za, p3.z, fmaf(ya, p3.y, fmaf(xa, p3.x, -p3.w)));
                float s1, s2, s3, s4;
                sort4_full(u0, u1, u2, u3, s1, s2, s3, s4);
                merge4(a1, a2, a3, a4, s1, s2, s3, s4);
            }
            {
                float u0 = fmaf(zb, p0.z, fmaf(yb, p0.y, fmaf(xb, p0.x, -p0.w)));
                float u1 = fmaf(zb, p1.z, fmaf(yb, p1.y, fmaf(xb, p1.x, -p1.w)));
                float u2 = fmaf(zb, p2.z, fmaf(yb, p2.y, fmaf(xb, p2.x, -p2.w)));
                float u3 = fmaf(zb, p3.z, fmaf(yb, p3.y, fmaf(xb, p3.x, -p3.w)));
                float s1, s2, s3, s4;
                sort4_full(u0, u1, u2, u3, s1, s2, s3, s4);
                merge4(b1, b2, b3, b4, s1, s2, s3, s4);
            }
        }
    }

    g_cand[blockIdx.y * NPTS + i0] = make_float4(a1, a2, a3, a4);
    g_cand[blockIdx.y * NPTS + i1] = make_float4(b1, b2, b3, b4);

    // ---- fused merge: last-arriving block of this tile ----
    __threadfence();
    __shared__ int sLast;
    if (tid == 0)
        sLast = (atomicAdd(&g_cnt[tile], 1) == CH - 1) ? 1 : 0;
    __syncthreads();
    if (!sLast) return;
    __threadfence();

    #pragma unroll
    for (int k = 0; k < 2; ++k) {
        const int i = tile * TILE + tid + k * TPB;
        const float4 me = (k == 0) ? meA : meB;

        float4 c0 = g_cand[0 * NPTS + i];
        float w1 = c0.x, w2 = c0.y, w3 = c0.z, w4 = c0.w;
        #pragma unroll
        for (int s = 1; s < CH; ++s) {
            float4 cc = g_cand[s * NPTS + i];
            merge4(w1, w2, w3, w4, cc.x, cc.y, cc.z, cc.w);
        }
        // w1 == u_self (strict global max within range); NNs are w2..w4.
        const float sqi = me.x * me.x + me.y * me.y + me.z * me.z;
        float e1 = fmaxf(fmaf(-2.0f, w2, sqi), 0.0f);   // d^2 ascending
        float e2 = fmaxf(fmaf(-2.0f, w3, sqi), 0.0f);
        float e3 = fmaxf(fmaf(-2.0f, w4, sqi), 0.0f);
        float d3 = sqrtf(e3);

        // exactness: radial shell ball [r-d3, r+d3] (+-1 bin float-fuzz guard)
        // must lie within scanned shells
        float r = sqrtf(sqi);
        int bl = max(binf(r - d3) - 1, 0);
        int bh = min(binf(r + d3) + 1, NZ - 1);
        if (bl >= zlo && bh <= zhi) {
            write_cov(e1, e2, e3, __float_as_int(me.w), quat, out);
        } else {
            int pos = atomicAdd(&g_failCnt, 1);
            g_failList[pos] = i;                   // delta-scan finishes it
            g_failD[pos]    = make_float4(e1, e2, e3, d3);
        }
    }

    if (tid == 0) g_cnt[tile] = 0;             // reset for next graph replay
}

// ---- K4: delta fallback — warp-per-failure over uncovered shells ---------
// Delta shells [bl, zlo) and (zhi, bh] are disjoint from the chunk-scanned
// region; with radial binning these are small for every radius class.
// Fresh warp triple merged ONCE (lane 0) with the stored triple.
__global__ __launch_bounds__(256)
void fallback_kernel(const float* __restrict__ quat, float* __restrict__ out) {
    const int gw   = (blockIdx.x * 256 + threadIdx.x) >> 5;
    const int lane = threadIdx.x & 31;
    const int nf   = g_failCnt;

    for (int f = gw; f < nf; f += (FB_BLOCKS * 8)) {
        const int p     = g_failList[f];
        const float4 ed = g_failD[f];          // {e1,e2,e3,d3}
        const float4 me = g_sorted[p];

        // recompute the tile's scanned shell range (deterministic ints)
        const int tile = p / TILE;
        const int smin = g_sbin[tile * TILE];
        const int smax = g_sbin[tile * TILE + TILE - 1];
        const int zlo  = max(smin - MARG, 0);
        const int zhi  = min(smax + MARG, NZ - 1);

        float r = sqrtf(me.x * me.x + me.y * me.y + me.z * me.z);
        const int bl = max(binf(r - ed.w) - 1, 0);
        const int bh = min(binf(r + ed.w) + 1, NZ - 1);

        // two disjoint uncovered ranges (either may be empty)
        const int aLo = g_zStart[bl],               aHi = g_zStart[max(bl, zlo)];
        const int bLo = g_zStart[min(bh, zhi) + 1], bHi = g_zStart[bh + 1];

        float m1 = FINF, m2 = FINF, m3 = FINF;
        #pragma unroll 4
        for (int t = aLo + lane; t < aHi; t += 32) {
            float4 q = g_sorted[t];
            float dx = me.x - q.x, dy = me.y - q.y, dz = me.z - q.z;
            ins3(fmaf(dz, dz, fmaf(dy, dy, dx * dx)), m1, m2, m3);
        }
        #pragma unroll 4
        for (int t = bLo + lane; t < bHi; t += 32) {
            float4 q = g_sorted[t];
            float dx = me.x - q.x, dy = me.y - q.y, dz = me.z - q.z;
            ins3(fmaf(dz, dz, fmaf(dy, dy, dx * dx)), m1, m2, m3);
        }
        #pragma unroll
        for (int off = 16; off >= 1; off >>= 1) {
            float s1 = __shfl_xor_sync(FULLMASK, m1, off);
            float s2 = __shfl_xor_sync(FULLMASK, m2, off);
            float s3 = __shfl_xor_sync(FULLMASK, m3, off);
            merge3asc(m1, m2, m3, s1, s2, s3);
        }
        if (lane == 0) {
            merge3asc(m1, m2, m3, ed.x, ed.y, ed.z);   // union with scanned triple
            write_cov(m1, m2, m3, __float_as_int(me.w), quat, out);
        }
    }

    // restore zero-invariants for the next graph replay
    if (blockIdx.x == 0 && threadIdx.x < NZ) {
        g_zhist[threadIdx.x] = 0;
        g_zcur[threadIdx.x]  = 0;
    }
}

extern "C" void kernel_launch(void* const* d_in, const int* in_sizes, int n_in,
                              void* d_out, int out_size) {
    const float* pts  = (const float*)d_in[0];   // (N, 3) float32
    const float* quat = (const float*)d_in[1];   // (N, 4) float32
    float* out = (float*)d_out;                  // (N, 3, 3) float32

    bin_kernel     <<<(NPTS + 255) / 256, 256>>>(pts);
    scatter_kernel <<<(NPTS + 255) / 256, 256>>>(pts);
    dim3 grid(NTILE, CH);
    chunk_kernel   <<<grid, TPB>>>(quat, out);
    fallback_kernel<<<FB_BLOCKS, 256>>>(quat, out);
}